// round 16
// baseline (speedup 1.0000x reference)
#include <cuda_runtime.h>
#include <cuda_bf16.h>
#include <cuda_fp16.h>
#include <stdint.h>

#define BROWS 8192
#define NHID  512
#define NN    50000
#define NNP   50176           // 392*128
#define NC    40
#define KNE   40
#define CAND  64
#define EPSF  1e-5f

// GEMM config: fp16 HMMA, f32 acc, BK=64, frag double-buffer, 2 CTAs/SM
#define MT    128
#define NT    128
#define BK    64
#define KT    (NHID / BK)     // 8
#define NSTG  3
#define LDSS  72
#define LDSB  (LDSS * 2)      // 144 bytes
#define STG_BYTES ((MT + NT) * LDSB)        // 36864
#define SMEM_BYTES (NSTG * STG_BYTES)       // 110592
#define GTHREADS 128

// select config
#define SBUF 4096
#define CHNK 2048
#define NBIN 2048
#define SEL_DELTA 0.044f      // z~2.0 above per-row mean (R11-proven)

// ---------------- scratch ----------------
__device__ __half g_featn16[BROWS * NHID];
__device__ __half g_memn16[(size_t)NNP * NHID];
__device__ float  g_mem_inv[NN];
__device__ __nv_bfloat16 g_sim[(size_t)BROWS * NNP];
__device__ float  g_lse[BROWS];
__device__ float  g_colsum[NHID];
__device__ float  g_rowmean[BROWS];
__device__ float  g_ent_sum;
__device__ float  g_cls_sum[NC];
__device__ float  g_loss;

// ---------------- helpers ----------------
__device__ __forceinline__ uint32_t smem_u32(const void* p) {
    return (uint32_t)__cvta_generic_to_shared(p);
}
__device__ __forceinline__ void cpa16(uint32_t s, const void* g) {
    asm volatile("cp.async.cg.shared.global [%0], [%1], 16;" :: "r"(s), "l"(g));
}
__device__ __forceinline__ void ldsm4(uint32_t* r, uint32_t a) {
    asm volatile("ldmatrix.sync.aligned.m8n8.x4.shared.b16 {%0,%1,%2,%3}, [%4];"
                 : "=r"(r[0]), "=r"(r[1]), "=r"(r[2]), "=r"(r[3]) : "r"(a));
}
__device__ __forceinline__ void mma_f32acc(float* c, const uint32_t* a, const uint32_t* b) {
    asm volatile(
        "mma.sync.aligned.m16n8k16.row.col.f32.f16.f16.f32 "
        "{%0,%1,%2,%3}, {%4,%5,%6,%7}, {%8,%9}, {%0,%1,%2,%3};"
        : "+f"(c[0]), "+f"(c[1]), "+f"(c[2]), "+f"(c[3])
        : "r"(a[0]), "r"(a[1]), "r"(a[2]), "r"(a[3]), "r"(b[0]), "r"(b[1]));
}

// ---------------- init ----------------
__global__ void k_init() {
    int t = threadIdx.x;
    if (t < NC) g_cls_sum[t] = 0.f;
    if (t == NC) g_ent_sum = 0.f;
    if (t == NC + 1) g_loss = 0.f;
}

// ---------------- softmax stats ----------------
__global__ __launch_bounds__(256) void k_softmax_stats(const float* __restrict__ cls) {
    int row = blockIdx.x * 256 + threadIdx.x;
    float p[NC];
    const float* x = cls + (size_t)row * NC;
    float m = -1e30f;
#pragma unroll
    for (int j = 0; j < NC; j++) { float v = x[j]; p[j] = v; m = fmaxf(m, v); }
    float s = 0.f;
#pragma unroll
    for (int j = 0; j < NC; j++) { p[j] = expf(p[j] - m); s += p[j]; }
    float inv = 1.f / s;
    g_lse[row] = m + logf(s);
    float ent = 0.f;
#pragma unroll
    for (int j = 0; j < NC; j++) { p[j] *= inv; ent -= p[j] * logf(p[j] + EPSF); }
    const unsigned full = 0xffffffffu;
#pragma unroll
    for (int o = 16; o; o >>= 1) ent += __shfl_xor_sync(full, ent, o);
#pragma unroll
    for (int j = 0; j < NC; j++) {
        float q = p[j];
#pragma unroll
        for (int o = 16; o; o >>= 1) q += __shfl_xor_sync(full, q, o);
        if ((threadIdx.x & 31) == 0) atomicAdd(&g_cls_sum[j], q);
    }
    if ((threadIdx.x & 31) == 0) atomicAdd(&g_ent_sum, ent);
}

// ---------------- L2 normalize feat -> fp16 (block 0 zeroes colsum) ----------
__global__ __launch_bounds__(128) void k_norm_feat(const float* __restrict__ f) {
    int row = blockIdx.x, t = threadIdx.x;
    if (row == 0) {
#pragma unroll
        for (int i = 0; i < 4; i++) g_colsum[t + i * 128] = 0.f;
    }
    const float* x = f + (size_t)row * NHID;
    float v[4]; float ss = 0.f;
#pragma unroll
    for (int i = 0; i < 4; i++) { v[i] = x[t + i * 128]; ss += v[i] * v[i]; }
    const unsigned full = 0xffffffffu;
#pragma unroll
    for (int o = 16; o; o >>= 1) ss += __shfl_xor_sync(full, ss, o);
    __shared__ float r4[4]; __shared__ float sInv;
    if ((t & 31) == 0) r4[t >> 5] = ss;
    __syncthreads();
    if (t == 0) sInv = 1.f / fmaxf(sqrtf(r4[0] + r4[1] + r4[2] + r4[3]), 1e-12f);
    __syncthreads();
    float inv = sInv;
#pragma unroll
    for (int i = 0; i < 4; i++)
        g_featn16[(size_t)row * NHID + t + i * 128] = __float2half_rn(v[i] * inv);
}

// ---------------- L2 normalize mem -> fp16 + inv norms (zero pad rows) ----------------
__global__ __launch_bounds__(128) void k_norm_mem(const float* __restrict__ f) {
    int row = blockIdx.x, t = threadIdx.x;
    if (row >= NN) {
#pragma unroll
        for (int i = 0; i < 4; i++)
            g_memn16[(size_t)row * NHID + t + i * 128] = __float2half_rn(0.f);
        return;
    }
    const float* x = f + (size_t)row * NHID;
    float v[4]; float ss = 0.f;
#pragma unroll
    for (int i = 0; i < 4; i++) { v[i] = x[t + i * 128]; ss += v[i] * v[i]; }
    const unsigned full = 0xffffffffu;
#pragma unroll
    for (int o = 16; o; o >>= 1) ss += __shfl_xor_sync(full, ss, o);
    __shared__ float r4[4]; __shared__ float sInv;
    if ((t & 31) == 0) r4[t >> 5] = ss;
    __syncthreads();
    if (t == 0) {
        float inv = 1.f / fmaxf(sqrtf(r4[0] + r4[1] + r4[2] + r4[3]), 1e-12f);
        sInv = inv; g_mem_inv[row] = inv;
    }
    __syncthreads();
    float inv = sInv;
#pragma unroll
    for (int i = 0; i < 4; i++)
        g_memn16[(size_t)row * NHID + t + i * 128] = __float2half_rn(v[i] * inv);
}

// ---------------- column sums of mem_norm (register-private, few atomics) ----------
__global__ __launch_bounds__(256) void k_colmean() {
    int t = threadIdx.x;
    float ax = 0.f, ay = 0.f;
    for (int r = blockIdx.x; r < NN; r += 256) {
        __half2 h = ((const __half2*)(g_memn16 + (size_t)r * NHID))[t];
        float2 f = __half22float2(h);
        ax += f.x; ay += f.y;
    }
    atomicAdd(&g_colsum[2 * t], ax);
    atomicAdd(&g_colsum[2 * t + 1], ay);
}

// ---------------- per-row sim mean: featn16 . colmean ----------------
__global__ __launch_bounds__(128) void k_rowmean() {
    int row = blockIdx.x, t = threadIdx.x;
    float s = 0.f;
#pragma unroll
    for (int i = 0; i < 4; i++) {
        int k = t + i * 128;
        s += __half2float(g_featn16[(size_t)row * NHID + k]) * g_colsum[k];
    }
    const unsigned full = 0xffffffffu;
#pragma unroll
    for (int o = 16; o; o >>= 1) s += __shfl_xor_sync(full, s, o);
    __shared__ float r4[4];
    if ((t & 31) == 0) r4[t >> 5] = s;
    __syncthreads();
    if (t == 0) g_rowmean[row] = (r4[0] + r4[1] + r4[2] + r4[3]) * (1.f / NN);
}

// ---------------- fp16 GEMM: 128 thr, 2 CTAs/SM, warptile 64x64 ----------
extern __shared__ __align__(16) uint8_t smem_g8[];

__global__ __launch_bounds__(GTHREADS, 2) void k_gemm() {
    const int tid = threadIdx.x, lane = tid & 31, wid = tid >> 5;
    const int bm = blockIdx.x, bn = blockIdx.y;
    const int wm = wid & 1, wn = wid >> 1;

    float acc[4][8][4];
#pragma unroll
    for (int mt = 0; mt < 4; mt++)
#pragma unroll
        for (int nt = 0; nt < 8; nt++)
#pragma unroll
            for (int i = 0; i < 4; i++) acc[mt][nt][i] = 0.f;

    uint32_t af[2][4][4];
    uint32_t bf[2][8][2];

    const __half* Ag = g_featn16 + (size_t)bm * MT * NHID;
    const __half* Bg = g_memn16 + (size_t)bn * NT * NHID;

    uint32_t sbase = smem_u32(smem_g8);
    uint32_t sA[NSTG], sB[NSTG];
#pragma unroll
    for (int s = 0; s < NSTG; s++) {
        sA[s] = sbase + s * STG_BYTES;
        sB[s] = sA[s] + MT * LDSB;
    }

    auto LOAD = [&](int s, int kt) {
        const __half* Agt = Ag + kt * BK;
        const __half* Bgt = Bg + kt * BK;
#pragma unroll
        for (int i = 0; i < 8; i++) {
            int id = tid + i * GTHREADS; int r = id >> 3, c = id & 7;
            cpa16(sA[s] + r * LDSB + c * 16, Agt + (size_t)r * NHID + c * 8);
        }
#pragma unroll
        for (int i = 0; i < 8; i++) {
            int id = tid + i * GTHREADS; int r = id >> 3, c = id & 7;
            cpa16(sB[s] + r * LDSB + c * 16, Bgt + (size_t)r * NHID + c * 8);
        }
        asm volatile("cp.async.commit_group;");
    };

    const uint32_t aOff = (uint32_t)((wm * 64 + (lane & 15)) * LDSB + (lane >> 4) * 16);
    const uint32_t bOff = (uint32_t)((wn * 64 + (lane & 7) + ((lane >> 4) & 1) * 8) * LDSB
                                     + ((lane >> 3) & 1) * 16);

    auto LDFRAG = [&](int buf, uint32_t sa, uint32_t sb, int ks) {
#pragma unroll
        for (int mt = 0; mt < 4; mt++)
            ldsm4(af[buf][mt], sa + aOff + mt * 16 * LDSB + ks * 32);
#pragma unroll
        for (int ntp = 0; ntp < 4; ntp++) {
            uint32_t r[4];
            ldsm4(r, sb + bOff + ntp * 16 * LDSB + ks * 32);
            bf[buf][2 * ntp][0] = r[0]; bf[buf][2 * ntp][1] = r[1];
            bf[buf][2 * ntp + 1][0] = r[2]; bf[buf][2 * ntp + 1][1] = r[3];
        }
    };

    auto MMAALL = [&](int buf) {
#pragma unroll
        for (int mt = 0; mt < 4; mt++)
#pragma unroll
            for (int nt = 0; nt < 8; nt++)
                mma_f32acc(acc[mt][nt], af[buf][mt], bf[buf][nt]);
    };

    LOAD(0, 0);
    LOAD(1, 1);
    asm volatile("cp.async.wait_group 1;");
    __syncthreads();
    LDFRAG(0, sA[0], sB[0], 0);

#pragma unroll
    for (int kt = 0; kt < KT; kt++) {
        const int s = kt % NSTG;
        if (kt + 2 < KT) LOAD((kt + 2) % NSTG, kt + 2);
        LDFRAG(1, sA[s], sB[s], 1);
        MMAALL(0);
        LDFRAG(0, sA[s], sB[s], 2);
        MMAALL(1);
        LDFRAG(1, sA[s], sB[s], 3);
        MMAALL(0);
        if (kt + 1 < KT) {
            if (kt + 2 < KT) asm volatile("cp.async.wait_group 1;");
            else             asm volatile("cp.async.wait_group 0;");
            __syncthreads();
            LDFRAG(0, sA[(kt + 1) % NSTG], sB[(kt + 1) % NSTG], 0);
        }
        MMAALL(1);
    }

    // epilogue -> bf16 sim
#pragma unroll
    for (int mt = 0; mt < 4; mt++)
#pragma unroll
        for (int nt = 0; nt < 8; nt++) {
            int r = bm * MT + wm * 64 + mt * 16 + (lane >> 2);
            int c = bn * NT + wn * 64 + nt * 8 + (lane & 3) * 2;
            *(__nv_bfloat162*)(g_sim + (size_t)r * NNP + c) =
                __floats2bfloat162_rn(acc[mt][nt][0], acc[mt][nt][1]);
            *(__nv_bfloat162*)(g_sim + (size_t)(r + 8) * NNP + c) =
                __floats2bfloat162_rn(acc[mt][nt][2], acc[mt][nt][3]);
        }
}

// ---------------- fused select + rescore + vote + cls_loss ----------------
__device__ __forceinline__ uint32_t f2key(float v) {
    uint32_t u = __float_as_uint(v) >> 16;
    return (u & 0x8000u) ? (0xFFFFu - u) : (u | 0x8000u);
}
__device__ __forceinline__ float key2f(uint32_t key) {
    uint32_t u = (key >= 0x8000u) ? (key & 0x7FFFu) : (0xFFFFu - key);
    return __uint_as_float(u << 16);
}

struct SelShared {
    float    bv[SBUF];
    int      bi[SBUF];
    uint32_t hist[NBIN];
    uint32_t psum[256];
    int      cnt;
    float    thr;
};

__device__ void hist_thr(SelShared* sh) {
    int tid = threadIdx.x;
    uint32_t s = 0;
#pragma unroll
    for (int j = 0; j < 8; j++) s += sh->hist[tid * 8 + j];
    sh->psum[tid] = s; __syncthreads();
    for (int off = 1; off < 256; off <<= 1) {
        uint32_t v = sh->psum[tid] + ((tid + off < 256) ? sh->psum[tid + off] : 0u);
        __syncthreads(); sh->psum[tid] = v; __syncthreads();
    }
    uint32_t sfx = sh->psum[tid];
    uint32_t nxt = (tid < 255) ? sh->psum[tid + 1] : 0u;
    if (sfx >= CAND && nxt < CAND) {
        uint32_t run = nxt; int b = tid * 8;
        for (int j = 7; j >= 0; j--) {
            run += sh->hist[tid * 8 + j];
            if (run >= CAND) { b = tid * 8 + j; break; }
        }
        sh->thr = key2f((uint32_t)b << 5);
    }
    __syncthreads();
}

__device__ void sel_compact(SelShared* sh) {
    int tid = threadIdx.x;
    for (int i = tid; i < NBIN; i += 256) sh->hist[i] = 0;
    __syncthreads();
    int n = sh->cnt; if (n > SBUF) n = SBUF;
    for (int e = tid; e < n; e += 256) atomicAdd(&sh->hist[f2key(sh->bv[e]) >> 5], 1u);
    __syncthreads();
    hist_thr(sh);
    float thr = sh->thr;
    float rv[16]; int ri[16]; int rn = 0;
    for (int e = tid; e < n; e += 256) {
        float v = sh->bv[e];
        if (v >= thr && rn < 16) { rv[rn] = v; ri[rn] = sh->bi[e]; rn++; }
    }
    __syncthreads();
    if (tid == 0) sh->cnt = 0;
    __syncthreads();
    int p = atomicAdd(&sh->cnt, rn);
    for (int j = 0; j < rn; j++) { sh->bv[p + j] = rv[j]; sh->bi[p + j] = ri[j]; }
    __syncthreads();
}

__global__ __launch_bounds__(256) void k_selres(const float* __restrict__ feat,
                                                const float* __restrict__ mem_fea,
                                                const float* __restrict__ mem_cls,
                                                const float* __restrict__ cls) {
    __shared__ SelShared sh;
    __shared__ __align__(16) float sfeat[NHID];
    __shared__ float cv[CAND]; __shared__ int ci[CAND];
    __shared__ float nb[NC];
    __shared__ float sInv;

    int row = blockIdx.x, tid = threadIdx.x, lane = tid & 31, wid = tid >> 5;
    const unsigned full = 0xffffffffu;

    // phase 0: load feat row (fp32), normalize exactly, stash in shared
    {
        float a = feat[(size_t)row * NHID + tid];
        float b = feat[(size_t)row * NHID + tid + 256];
        float ss = a * a + b * b;
#pragma unroll
        for (int o = 16; o; o >>= 1) ss += __shfl_xor_sync(full, ss, o);
        if ((tid & 31) == 0) sh.psum[tid >> 5] = __float_as_uint(ss);
        __syncthreads();
        if (tid == 0) {
            float tot = 0.f;
            for (int w = 0; w < 8; w++) tot += __uint_as_float(sh.psum[w]);
            sInv = 1.f / fmaxf(sqrtf(tot), 1e-12f);
            sh.cnt = 0;
        }
        __syncthreads();
        float inv = sInv;
        sfeat[tid] = a * inv;
        sfeat[tid + 256] = b * inv;
        if (tid < NC) nb[tid] = 0.f;
    }
    __syncthreads();

    const __nv_bfloat16* srow = g_sim + (size_t)row * NNP;
    float thr = g_rowmean[row] + SEL_DELTA;

    // phase 1: single sweep insert (~1100 expected)
    for (int base = 0; base < NN; base += CHNK) {
        int i0 = base + tid * 8;
        if (i0 < NN) {
            uint4 pk = *(const uint4*)(srow + i0);
            uint32_t ws[4] = {pk.x, pk.y, pk.z, pk.w};
#pragma unroll
            for (int q = 0; q < 4; q++) {
                float v0 = __uint_as_float((ws[q] & 0xFFFFu) << 16);
                float v1 = __uint_as_float(ws[q] & 0xFFFF0000u);
                int id0 = i0 + 2 * q, id1 = i0 + 2 * q + 1;
                if (v0 >= thr && id0 < NN) { int p = atomicAdd(&sh.cnt, 1); if (p < SBUF) { sh.bv[p] = v0; sh.bi[p] = id0; } }
                if (v1 >= thr && id1 < NN) { int p = atomicAdd(&sh.cnt, 1); if (p < SBUF) { sh.bv[p] = v1; sh.bi[p] = id1; } }
            }
        }
    }
    __syncthreads();

    if (sh.cnt < CAND || sh.cnt > SBUF) {
        // fallback: exact histogram over the row, then re-insert
        for (int i = tid; i < NBIN; i += 256) sh.hist[i] = 0;
        __syncthreads();
        for (int base = 0; base < NN; base += CHNK) {
            int i0 = base + tid * 8;
            if (i0 < NN) {
                uint4 pk = *(const uint4*)(srow + i0);
                uint32_t ws[4] = {pk.x, pk.y, pk.z, pk.w};
#pragma unroll
                for (int q = 0; q < 4; q++) {
                    int id0 = i0 + 2 * q, id1 = i0 + 2 * q + 1;
                    float v0 = __uint_as_float((ws[q] & 0xFFFFu) << 16);
                    float v1 = __uint_as_float(ws[q] & 0xFFFF0000u);
                    if (id0 < NN) atomicAdd(&sh.hist[f2key(v0) >> 5], 1u);
                    if (id1 < NN) atomicAdd(&sh.hist[f2key(v1) >> 5], 1u);
                }
            }
        }
        __syncthreads();
        hist_thr(&sh);
        float fthr = sh.thr;
        if (tid == 0) sh.cnt = 0;
        __syncthreads();
        for (int base = 0; base < NN; base += CHNK) {
            int i0 = base + tid * 8;
            if (i0 < NN) {
                uint4 pk = *(const uint4*)(srow + i0);
                uint32_t ws[4] = {pk.x, pk.y, pk.z, pk.w};
#pragma unroll
                for (int q = 0; q < 4; q++) {
                    float v0 = __uint_as_float((ws[q] & 0xFFFFu) << 16);
                    float v1 = __uint_as_float(ws[q] & 0xFFFF0000u);
                    int id0 = i0 + 2 * q, id1 = i0 + 2 * q + 1;
                    if (v0 >= fthr && id0 < NN) { int p = atomicAdd(&sh.cnt, 1); if (p < SBUF) { sh.bv[p] = v0; sh.bi[p] = id0; } }
                    if (v1 >= fthr && id1 < NN) { int p = atomicAdd(&sh.cnt, 1); if (p < SBUF) { sh.bv[p] = v1; sh.bi[p] = id1; } }
                }
            }
        }
        __syncthreads();
    }

    for (int it = 0; it < 3; it++) {
        if (sh.cnt <= 640) break;
        sel_compact(&sh);
        __syncthreads();
    }
    int m = sh.cnt; if (m > SBUF) m = SBUF;
    __syncthreads();
    // exact top-CAND by rank (index tiebreak) -> ci[] in shared
    for (int e = tid; e < m; e += 256) {
        float v = sh.bv[e]; int id = sh.bi[e]; int r = 0;
        for (int j = 0; j < m; j++) {
            float vj = sh.bv[j];
            r += (vj > v) || (vj == v && sh.bi[j] < id);
        }
        if (r < CAND) ci[r] = id;
    }
    __syncthreads();

    // phase 2: exact fp32 rescore of CAND candidates (float4 gather)
    const float4* sf4 = (const float4*)sfeat;
    for (int c = wid; c < CAND; c += 8) {
        int mm = ci[c];
        const float4* mr = (const float4*)(mem_fea + (size_t)mm * NHID);
        float s = 0.f;
#pragma unroll
        for (int i = 0; i < 4; i++) {
            int k4 = lane + i * 32;
            float4 a = sf4[k4];
            float4 b = mr[k4];
            s += a.x * b.x + a.y * b.y + a.z * b.z + a.w * b.w;
        }
#pragma unroll
        for (int o = 16; o; o >>= 1) s += __shfl_xor_sync(full, s, o);
        if (lane == 0) cv[c] = s * g_mem_inv[mm];
    }
    __syncthreads();

    // phase 3: rank candidates, vote, cls_loss
    if (tid < CAND) {
        float v = cv[tid]; int id = ci[tid]; int r = 0;
#pragma unroll 8
        for (int j = 0; j < CAND; j++) {
            float vj = cv[j];
            r += (vj > v) || (vj == v && ci[j] < id);
        }
        if (r >= 1 && r <= KNE) {
            const float* cr = mem_cls + (size_t)id * NC;
#pragma unroll
            for (int j = 0; j < NC; j++) atomicAdd(&nb[j], cr[j]);
        }
    }
    __syncthreads();

    if (tid == 0) {
        float best = -1e30f; int pred = 0;
#pragma unroll
        for (int j = 0; j < NC; j++) {
            float q = nb[j];
            if (q > best) { best = q; pred = j; }
        }
        float logp = cls[(size_t)row * NC + pred] - g_lse[row];
        atomicAdd(&g_loss, -logp * (1.f / BROWS));
    }
}

// ---------------- finalize ----------------
__global__ void k_final(float* __restrict__ out) {
    float ent = g_ent_sum * (1.f / BROWS);
    float div = 0.f;
#pragma unroll
    for (int j = 0; j < NC; j++) {
        float q = g_cls_sum[j] * (1.f / BROWS);
        div += q * logf(q + EPSF);
    }
    out[0] = ent + div + g_loss;
}

// ---------------- launch ----------------
extern "C" void kernel_launch(void* const* d_in, const int* in_sizes, int n_in,
                              void* d_out, int out_size) {
    const float* feat    = (const float*)d_in[0];
    const float* cls     = (const float*)d_in[1];
    const float* mem_fea = (const float*)d_in[2];
    const float* mem_cls = (const float*)d_in[3];
    float* out = (float*)d_out;

    cudaFuncSetAttribute(k_gemm, cudaFuncAttributeMaxDynamicSharedMemorySize, SMEM_BYTES);

    k_norm_feat<<<BROWS, 128>>>(feat);      // zeroes colsum (block 0)
    k_norm_mem<<<NNP, 128>>>(mem_fea);
    k_colmean<<<256, 256>>>();
    k_gemm<<<dim3(BROWS / MT, NNP / NT), GTHREADS, SMEM_BYTES>>>();  // ncu slot 4
    k_rowmean<<<BROWS, 128>>>();
    k_init<<<1, 64>>>();
    k_softmax_stats<<<BROWS / 256, 256>>>(cls);
    k_selres<<<BROWS, 256>>>(feat, mem_fea, mem_cls, cls);
    k_final<<<1, 1>>>(out);
}

// round 17
// speedup vs baseline: 1.2949x; 1.2949x over previous
#include <cuda_runtime.h>
#include <cuda_bf16.h>
#include <cuda_fp16.h>
#include <stdint.h>

#define BROWS 8192
#define NHID  512
#define NN    50000
#define NNP   50176           // 392*128
#define NC    40
#define KNE   40
#define CAND  64
#define EPSF  1e-5f

// GEMM config: fp16 HMMA, f32 acc, BK=64, frag double-buffer, 2 CTAs/SM
#define MT    128
#define NT    128
#define BK    64
#define KT    (NHID / BK)     // 8
#define NSTG  3
#define LDSS  72
#define LDSB  (LDSS * 2)      // 144 bytes
#define STG_BYTES ((MT + NT) * LDSB)        // 36864
#define SMEM_BYTES (NSTG * STG_BYTES)       // 110592
#define GTHREADS 128

// select config
#define SBUF 4096
#define CHNK 2048
#define NBIN 2048
#define SEL_DELTA 0.044f      // z~2.0 above per-row mean (R11-proven)

// ---------------- scratch ----------------
__device__ __half g_featn16[BROWS * NHID];
__device__ float  g_featn32[BROWS * NHID];
__device__ __half g_memn16[(size_t)NNP * NHID];
__device__ float  g_mem_inv[NN];
__device__ __nv_bfloat16 g_sim[(size_t)BROWS * NNP];
__device__ int    g_cand[BROWS * CAND];
__device__ float  g_lse[BROWS];
__device__ float  g_colsum[NHID];
__device__ float  g_rowmean[BROWS];
__device__ float  g_ent_sum;
__device__ float  g_cls_sum[NC];
__device__ float  g_loss;

// ---------------- helpers ----------------
__device__ __forceinline__ uint32_t smem_u32(const void* p) {
    return (uint32_t)__cvta_generic_to_shared(p);
}
__device__ __forceinline__ void cpa16(uint32_t s, const void* g) {
    asm volatile("cp.async.cg.shared.global [%0], [%1], 16;" :: "r"(s), "l"(g));
}
__device__ __forceinline__ void ldsm4(uint32_t* r, uint32_t a) {
    asm volatile("ldmatrix.sync.aligned.m8n8.x4.shared.b16 {%0,%1,%2,%3}, [%4];"
                 : "=r"(r[0]), "=r"(r[1]), "=r"(r[2]), "=r"(r[3]) : "r"(a));
}
__device__ __forceinline__ void mma_f32acc(float* c, const uint32_t* a, const uint32_t* b) {
    asm volatile(
        "mma.sync.aligned.m16n8k16.row.col.f32.f16.f16.f32 "
        "{%0,%1,%2,%3}, {%4,%5,%6,%7}, {%8,%9}, {%0,%1,%2,%3};"
        : "+f"(c[0]), "+f"(c[1]), "+f"(c[2]), "+f"(c[3])
        : "r"(a[0]), "r"(a[1]), "r"(a[2]), "r"(a[3]), "r"(b[0]), "r"(b[1]));
}

// ---------------- softmax stats ----------------
__global__ __launch_bounds__(256) void k_softmax_stats(const float* __restrict__ cls) {
    int row = blockIdx.x * 256 + threadIdx.x;
    float p[NC];
    const float* x = cls + (size_t)row * NC;
    float m = -1e30f;
#pragma unroll
    for (int j = 0; j < NC; j++) { float v = x[j]; p[j] = v; m = fmaxf(m, v); }
    float s = 0.f;
#pragma unroll
    for (int j = 0; j < NC; j++) { p[j] = expf(p[j] - m); s += p[j]; }
    float inv = 1.f / s;
    g_lse[row] = m + logf(s);
    float ent = 0.f;
#pragma unroll
    for (int j = 0; j < NC; j++) { p[j] *= inv; ent -= p[j] * logf(p[j] + EPSF); }
    const unsigned full = 0xffffffffu;
#pragma unroll
    for (int o = 16; o; o >>= 1) ent += __shfl_xor_sync(full, ent, o);
#pragma unroll
    for (int j = 0; j < NC; j++) {
        float q = p[j];
#pragma unroll
        for (int o = 16; o; o >>= 1) q += __shfl_xor_sync(full, q, o);
        if ((threadIdx.x & 31) == 0) atomicAdd(&g_cls_sum[j], q);
    }
    if ((threadIdx.x & 31) == 0) atomicAdd(&g_ent_sum, ent);
}

// ---------------- L2 normalize feat -> fp32 + fp16 (block 0: init scalars) ----------
__global__ __launch_bounds__(128) void k_norm_feat(const float* __restrict__ f) {
    int row = blockIdx.x, t = threadIdx.x;
    if (row == 0) {
#pragma unroll
        for (int i = 0; i < 4; i++) g_colsum[t + i * 128] = 0.f;
        if (t < NC) g_cls_sum[t] = 0.f;
        if (t == NC) g_ent_sum = 0.f;
        if (t == NC + 1) g_loss = 0.f;
    }
    const float* x = f + (size_t)row * NHID;
    float v[4]; float ss = 0.f;
#pragma unroll
    for (int i = 0; i < 4; i++) { v[i] = x[t + i * 128]; ss += v[i] * v[i]; }
    const unsigned full = 0xffffffffu;
#pragma unroll
    for (int o = 16; o; o >>= 1) ss += __shfl_xor_sync(full, ss, o);
    __shared__ float r4[4]; __shared__ float sInv;
    if ((t & 31) == 0) r4[t >> 5] = ss;
    __syncthreads();
    if (t == 0) sInv = 1.f / fmaxf(sqrtf(r4[0] + r4[1] + r4[2] + r4[3]), 1e-12f);
    __syncthreads();
    float inv = sInv;
#pragma unroll
    for (int i = 0; i < 4; i++) {
        float nv = v[i] * inv;
        size_t o = (size_t)row * NHID + t + i * 128;
        g_featn32[o] = nv;
        g_featn16[o] = __float2half_rn(nv);
    }
}

// ---------------- L2 normalize mem -> fp16 + inv norms (zero pad rows) ----------------
__global__ __launch_bounds__(128) void k_norm_mem(const float* __restrict__ f) {
    int row = blockIdx.x, t = threadIdx.x;
    if (row >= NN) {
#pragma unroll
        for (int i = 0; i < 4; i++)
            g_memn16[(size_t)row * NHID + t + i * 128] = __float2half_rn(0.f);
        return;
    }
    const float* x = f + (size_t)row * NHID;
    float v[4]; float ss = 0.f;
#pragma unroll
    for (int i = 0; i < 4; i++) { v[i] = x[t + i * 128]; ss += v[i] * v[i]; }
    const unsigned full = 0xffffffffu;
#pragma unroll
    for (int o = 16; o; o >>= 1) ss += __shfl_xor_sync(full, ss, o);
    __shared__ float r4[4]; __shared__ float sInv;
    if ((t & 31) == 0) r4[t >> 5] = ss;
    __syncthreads();
    if (t == 0) {
        float inv = 1.f / fmaxf(sqrtf(r4[0] + r4[1] + r4[2] + r4[3]), 1e-12f);
        sInv = inv; g_mem_inv[row] = inv;
    }
    __syncthreads();
    float inv = sInv;
#pragma unroll
    for (int i = 0; i < 4; i++)
        g_memn16[(size_t)row * NHID + t + i * 128] = __float2half_rn(v[i] * inv);
}

// ---------------- column sums of mem_norm (register-private, few atomics) ----------
__global__ __launch_bounds__(256) void k_colmean() {
    int t = threadIdx.x;
    float ax = 0.f, ay = 0.f;
    for (int r = blockIdx.x; r < NN; r += 256) {
        __half2 h = ((const __half2*)(g_memn16 + (size_t)r * NHID))[t];
        float2 f = __half22float2(h);
        ax += f.x; ay += f.y;
    }
    atomicAdd(&g_colsum[2 * t], ax);
    atomicAdd(&g_colsum[2 * t + 1], ay);
}

// ---------------- per-row sim mean: feat_norm . colmean ----------------
__global__ __launch_bounds__(128) void k_rowmean() {
    int row = blockIdx.x, t = threadIdx.x;
    float s = 0.f;
#pragma unroll
    for (int i = 0; i < 4; i++)
        s += g_featn32[(size_t)row * NHID + t + i * 128] * g_colsum[t + i * 128];
    const unsigned full = 0xffffffffu;
#pragma unroll
    for (int o = 16; o; o >>= 1) s += __shfl_xor_sync(full, s, o);
    __shared__ float r4[4];
    if ((t & 31) == 0) r4[t >> 5] = s;
    __syncthreads();
    if (t == 0) g_rowmean[row] = (r4[0] + r4[1] + r4[2] + r4[3]) * (1.f / NN);
}

// ---------------- fp16 GEMM: 128 thr, 2 CTAs/SM, warptile 64x64 ----------
extern __shared__ __align__(16) uint8_t smem_g8[];

__global__ __launch_bounds__(GTHREADS, 2) void k_gemm() {
    const int tid = threadIdx.x, lane = tid & 31, wid = tid >> 5;
    const int bm = blockIdx.x, bn = blockIdx.y;
    const int wm = wid & 1, wn = wid >> 1;

    float acc[4][8][4];
#pragma unroll
    for (int mt = 0; mt < 4; mt++)
#pragma unroll
        for (int nt = 0; nt < 8; nt++)
#pragma unroll
            for (int i = 0; i < 4; i++) acc[mt][nt][i] = 0.f;

    uint32_t af[2][4][4];
    uint32_t bf[2][8][2];

    const __half* Ag = g_featn16 + (size_t)bm * MT * NHID;
    const __half* Bg = g_memn16 + (size_t)bn * NT * NHID;

    uint32_t sbase = smem_u32(smem_g8);
    uint32_t sA[NSTG], sB[NSTG];
#pragma unroll
    for (int s = 0; s < NSTG; s++) {
        sA[s] = sbase + s * STG_BYTES;
        sB[s] = sA[s] + MT * LDSB;
    }

    auto LOAD = [&](int s, int kt) {
        const __half* Agt = Ag + kt * BK;
        const __half* Bgt = Bg + kt * BK;
#pragma unroll
        for (int i = 0; i < 8; i++) {
            int id = tid + i * GTHREADS; int r = id >> 3, c = id & 7;
            cpa16(sA[s] + r * LDSB + c * 16, Agt + (size_t)r * NHID + c * 8);
        }
#pragma unroll
        for (int i = 0; i < 8; i++) {
            int id = tid + i * GTHREADS; int r = id >> 3, c = id & 7;
            cpa16(sB[s] + r * LDSB + c * 16, Bgt + (size_t)r * NHID + c * 8);
        }
        asm volatile("cp.async.commit_group;");
    };

    const uint32_t aOff = (uint32_t)((wm * 64 + (lane & 15)) * LDSB + (lane >> 4) * 16);
    const uint32_t bOff = (uint32_t)((wn * 64 + (lane & 7) + ((lane >> 4) & 1) * 8) * LDSB
                                     + ((lane >> 3) & 1) * 16);

    auto LDFRAG = [&](int buf, uint32_t sa, uint32_t sb, int ks) {
#pragma unroll
        for (int mt = 0; mt < 4; mt++)
            ldsm4(af[buf][mt], sa + aOff + mt * 16 * LDSB + ks * 32);
#pragma unroll
        for (int ntp = 0; ntp < 4; ntp++) {
            uint32_t r[4];
            ldsm4(r, sb + bOff + ntp * 16 * LDSB + ks * 32);
            bf[buf][2 * ntp][0] = r[0]; bf[buf][2 * ntp][1] = r[1];
            bf[buf][2 * ntp + 1][0] = r[2]; bf[buf][2 * ntp + 1][1] = r[3];
        }
    };

    auto MMAALL = [&](int buf) {
#pragma unroll
        for (int mt = 0; mt < 4; mt++)
#pragma unroll
            for (int nt = 0; nt < 8; nt++)
                mma_f32acc(acc[mt][nt], af[buf][mt], bf[buf][nt]);
    };

    LOAD(0, 0);
    LOAD(1, 1);
    asm volatile("cp.async.wait_group 1;");
    __syncthreads();
    LDFRAG(0, sA[0], sB[0], 0);

#pragma unroll
    for (int kt = 0; kt < KT; kt++) {
        const int s = kt % NSTG;
        if (kt + 2 < KT) LOAD((kt + 2) % NSTG, kt + 2);
        LDFRAG(1, sA[s], sB[s], 1);
        MMAALL(0);
        LDFRAG(0, sA[s], sB[s], 2);
        MMAALL(1);
        LDFRAG(1, sA[s], sB[s], 3);
        MMAALL(0);
        if (kt + 1 < KT) {
            if (kt + 2 < KT) asm volatile("cp.async.wait_group 1;");
            else             asm volatile("cp.async.wait_group 0;");
            __syncthreads();
            LDFRAG(0, sA[(kt + 1) % NSTG], sB[(kt + 1) % NSTG], 0);
        }
        MMAALL(1);
    }

    // epilogue -> bf16 sim
#pragma unroll
    for (int mt = 0; mt < 4; mt++)
#pragma unroll
        for (int nt = 0; nt < 8; nt++) {
            int r = bm * MT + wm * 64 + mt * 16 + (lane >> 2);
            int c = bn * NT + wn * 64 + nt * 8 + (lane & 3) * 2;
            *(__nv_bfloat162*)(g_sim + (size_t)r * NNP + c) =
                __floats2bfloat162_rn(acc[mt][nt][0], acc[mt][nt][1]);
            *(__nv_bfloat162*)(g_sim + (size_t)(r + 8) * NNP + c) =
                __floats2bfloat162_rn(acc[mt][nt][2], acc[mt][nt][3]);
        }
}

// ---------------- per-row top-CAND selection (packed uint32 candidates) ----------
__device__ __forceinline__ uint32_t f2key(float v) {
    uint32_t u = __float_as_uint(v) >> 16;   // exact bf16 bits
    return (u & 0x8000u) ? (0xFFFFu - u) : (u | 0x8000u);
}
// pack: sortable value key in high 16, (0xFFFF - idx) in low 16.
// integer > on packed == (value greater) OR (value equal AND index smaller).
__device__ __forceinline__ uint32_t packcand(float v, int id) {
    return (f2key(v) << 16) | (0xFFFFu - (uint32_t)id);
}

struct SelShared {
    uint32_t pv[SBUF];
    uint32_t hist[NBIN];
    uint32_t psum[256];
    int      cnt;
    uint32_t thrkey;   // 16-bit key threshold (bin base)
};

// hist over 16-bit keys (bin = key >> 5); sets thrkey so count(key >= thrkey) >= CAND
__device__ void hist_thr(SelShared* sh) {
    int tid = threadIdx.x;
    uint32_t s = 0;
#pragma unroll
    for (int j = 0; j < 8; j++) s += sh->hist[tid * 8 + j];
    sh->psum[tid] = s; __syncthreads();
    for (int off = 1; off < 256; off <<= 1) {
        uint32_t v = sh->psum[tid] + ((tid + off < 256) ? sh->psum[tid + off] : 0u);
        __syncthreads(); sh->psum[tid] = v; __syncthreads();
    }
    uint32_t sfx = sh->psum[tid];
    uint32_t nxt = (tid < 255) ? sh->psum[tid + 1] : 0u;
    if (sfx >= CAND && nxt < CAND) {
        uint32_t run = nxt; int b = tid * 8;
        for (int j = 7; j >= 0; j--) {
            run += sh->hist[tid * 8 + j];
            if (run >= CAND) { b = tid * 8 + j; break; }
        }
        sh->thrkey = (uint32_t)b << 5;
    }
    __syncthreads();
}

__device__ void sel_compact(SelShared* sh) {
    int tid = threadIdx.x;
    for (int i = tid; i < NBIN; i += 256) sh->hist[i] = 0;
    __syncthreads();
    int n = sh->cnt; if (n > SBUF) n = SBUF;
    for (int e = tid; e < n; e += 256) atomicAdd(&sh->hist[sh->pv[e] >> 21], 1u);
    __syncthreads();
    hist_thr(sh);
    uint32_t thrp = sh->thrkey << 16;
    uint32_t rp[16]; int rn = 0;
    for (int e = tid; e < n; e += 256) {
        uint32_t p = sh->pv[e];
        if (p >= thrp && rn < 16) rp[rn++] = p;
    }
    __syncthreads();
    if (tid == 0) sh->cnt = 0;
    __syncthreads();
    int p0 = atomicAdd(&sh->cnt, rn);
    for (int j = 0; j < rn; j++) sh->pv[p0 + j] = rp[j];
    __syncthreads();
}

__global__ __launch_bounds__(256) void k_select() {
    __shared__ SelShared sh;
    int row = blockIdx.x, tid = threadIdx.x;
    if (tid == 0) sh.cnt = 0;
    __syncthreads();

    const __nv_bfloat16* srow = g_sim + (size_t)row * NNP;
    float thr = g_rowmean[row] + SEL_DELTA;

    // single sweep: insert values >= row-adaptive threshold (~1100 expected)
    for (int base = 0; base < NN; base += CHNK) {
        int i0 = base + tid * 8;
        if (i0 < NN) {
            uint4 pk = *(const uint4*)(srow + i0);
            uint32_t ws[4] = {pk.x, pk.y, pk.z, pk.w};
#pragma unroll
            for (int q = 0; q < 4; q++) {
                float v0 = __uint_as_float((ws[q] & 0xFFFFu) << 16);
                float v1 = __uint_as_float(ws[q] & 0xFFFF0000u);
                int id0 = i0 + 2 * q, id1 = i0 + 2 * q + 1;
                if (v0 >= thr && id0 < NN) { int p = atomicAdd(&sh.cnt, 1); if (p < SBUF) sh.pv[p] = packcand(v0, id0); }
                if (v1 >= thr && id1 < NN) { int p = atomicAdd(&sh.cnt, 1); if (p < SBUF) sh.pv[p] = packcand(v1, id1); }
            }
        }
    }
    __syncthreads();

    if (sh.cnt < CAND || sh.cnt > SBUF) {
        // fallback: exact key histogram over the row, then re-insert
        for (int i = tid; i < NBIN; i += 256) sh.hist[i] = 0;
        __syncthreads();
        for (int base = 0; base < NN; base += CHNK) {
            int i0 = base + tid * 8;
            if (i0 < NN) {
                uint4 pk = *(const uint4*)(srow + i0);
                uint32_t ws[4] = {pk.x, pk.y, pk.z, pk.w};
#pragma unroll
                for (int q = 0; q < 4; q++) {
                    int id0 = i0 + 2 * q, id1 = i0 + 2 * q + 1;
                    float v0 = __uint_as_float((ws[q] & 0xFFFFu) << 16);
                    float v1 = __uint_as_float(ws[q] & 0xFFFF0000u);
                    if (id0 < NN) atomicAdd(&sh.hist[f2key(v0) >> 5], 1u);
                    if (id1 < NN) atomicAdd(&sh.hist[f2key(v1) >> 5], 1u);
                }
            }
        }
        __syncthreads();
        hist_thr(&sh);
        uint32_t fthr = sh.thrkey;
        if (tid == 0) sh.cnt = 0;
        __syncthreads();
        for (int base = 0; base < NN; base += CHNK) {
            int i0 = base + tid * 8;
            if (i0 < NN) {
                uint4 pk = *(const uint4*)(srow + i0);
                uint32_t ws[4] = {pk.x, pk.y, pk.z, pk.w};
#pragma unroll
                for (int q = 0; q < 4; q++) {
                    float v0 = __uint_as_float((ws[q] & 0xFFFFu) << 16);
                    float v1 = __uint_as_float(ws[q] & 0xFFFF0000u);
                    int id0 = i0 + 2 * q, id1 = i0 + 2 * q + 1;
                    if (id0 < NN && f2key(v0) >= fthr) { int p = atomicAdd(&sh.cnt, 1); if (p < SBUF) sh.pv[p] = packcand(v0, id0); }
                    if (id1 < NN && f2key(v1) >= fthr) { int p = atomicAdd(&sh.cnt, 1); if (p < SBUF) sh.pv[p] = packcand(v1, id1); }
                }
            }
        }
        __syncthreads();
    }

    for (int it = 0; it < 3; it++) {
        if (sh.cnt <= 640) break;
        sel_compact(&sh);
        __syncthreads();
    }
    int m = sh.cnt; if (m > SBUF) m = SBUF;
    __syncthreads();
    // exact top-CAND by rank (packed compare: value desc, index asc)
    for (int e = tid; e < m; e += 256) {
        uint32_t p = sh.pv[e]; int r = 0;
        for (int j = 0; j < m; j++) r += (sh.pv[j] > p);
        if (r < CAND) g_cand[row * CAND + r] = (int)(0xFFFFu - (p & 0xFFFFu));
    }
}

// ---------------- exact fp32 rescore (float4 gather), vote, cls_loss ----------------
__global__ __launch_bounds__(256) void k_rescore(const float* __restrict__ mem_fea,
                                                 const float* __restrict__ mem_cls,
                                                 const float* __restrict__ cls) {
    int row = blockIdx.x, tid = threadIdx.x, lane = tid & 31, wid = tid >> 5;
    __shared__ __align__(16) float sfeat[NHID];
    __shared__ float cv[CAND]; __shared__ int ci[CAND];
    __shared__ float nb[NC];

    for (int k = tid; k < NHID; k += 256) sfeat[k] = g_featn32[(size_t)row * NHID + k];
    if (tid < CAND) ci[tid] = g_cand[row * CAND + tid];
    if (tid < NC) nb[tid] = 0.f;
    __syncthreads();

    const unsigned full = 0xffffffffu;
    const float4* sf4 = (const float4*)sfeat;
    for (int c = wid; c < CAND; c += 8) {
        int m = ci[c];
        const float4* mr = (const float4*)(mem_fea + (size_t)m * NHID);
        float s = 0.f;
#pragma unroll
        for (int i = 0; i < 4; i++) {
            int k4 = lane + i * 32;
            float4 a = sf4[k4];
            float4 b = mr[k4];
            s += a.x * b.x + a.y * b.y + a.z * b.z + a.w * b.w;
        }
#pragma unroll
        for (int o = 16; o; o >>= 1) s += __shfl_xor_sync(full, s, o);
        if (lane == 0) cv[c] = s * g_mem_inv[m];
    }
    __syncthreads();

    if (tid < CAND) {
        float v = cv[tid]; int id = ci[tid]; int r = 0;
#pragma unroll 8
        for (int j = 0; j < CAND; j++) {
            float vj = cv[j];
            r += (vj > v) || (vj == v && ci[j] < id);
        }
        if (r >= 1 && r <= KNE) {
            const float* cr = mem_cls + (size_t)id * NC;
#pragma unroll
            for (int j = 0; j < NC; j++) atomicAdd(&nb[j], cr[j]);
        }
    }
    __syncthreads();

    if (tid == 0) {
        float best = -1e30f; int pred = 0;
#pragma unroll
        for (int j = 0; j < NC; j++) {
            float q = nb[j];
            if (q > best) { best = q; pred = j; }
        }
        float logp = cls[(size_t)row * NC + pred] - g_lse[row];
        atomicAdd(&g_loss, -logp * (1.f / BROWS));
    }
}

// ---------------- finalize ----------------
__global__ void k_final(float* __restrict__ out) {
    float ent = g_ent_sum * (1.f / BROWS);
    float div = 0.f;
#pragma unroll
    for (int j = 0; j < NC; j++) {
        float q = g_cls_sum[j] * (1.f / BROWS);
        div += q * logf(q + EPSF);
    }
    out[0] = ent + div + g_loss;
}

// ---------------- launch ----------------
extern "C" void kernel_launch(void* const* d_in, const int* in_sizes, int n_in,
                              void* d_out, int out_size) {
    const float* feat    = (const float*)d_in[0];
    const float* cls     = (const float*)d_in[1];
    const float* mem_fea = (const float*)d_in[2];
    const float* mem_cls = (const float*)d_in[3];
    float* out = (float*)d_out;

    cudaFuncSetAttribute(k_gemm, cudaFuncAttributeMaxDynamicSharedMemorySize, SMEM_BYTES);

    k_norm_feat<<<BROWS, 128>>>(feat);      // block 0 zeroes colsum + scalars
    k_norm_mem<<<NNP, 128>>>(mem_fea);
    k_colmean<<<256, 256>>>();
    k_gemm<<<dim3(BROWS / MT, NNP / NT), GTHREADS, SMEM_BYTES>>>();  // ncu slot 4
    k_rowmean<<<BROWS, 128>>>();
    k_softmax_stats<<<BROWS / 256, 256>>>(cls);
    k_select<<<BROWS, 256>>>();
    k_rescore<<<BROWS, 256>>>(mem_fea, mem_cls, cls);
    k_final<<<1, 1>>>(out);
}